// round 5
// baseline (speedup 1.0000x reference)
#include <cuda_runtime.h>

// EmbeddingBlock: out = swish( [emb[z[s]] | emb[z[d]] | e_rbf@edge_W^T] @ dense_W^T + b )
//
// Factorization (VOCAB=100 distinct embedding rows):
//   P12[vs][vd] = emb[vs]@W[:, :128]^T + emb[vd]@W[:,128:256]^T + b  (100^2 x 272, 10.9 MB, L2-resident)
//   W3eff       = edge_W^T @ W[:,256:272]^T                          (16 x 272, register-resident)
// Per edge: out = swish( P12[pair[e]] + e_rbf[e] @ W3eff )
// R5 = R4 resubmit (infra failure): R2 body (2 edges/thread) + grid 1036 (7 CTAs/SM).

#define D    128
#define RBF  16
#define CAT  272
#define J4   68
#define VMAX 128
#define EMAX 1048576

__device__ float4 g_W3[RBF * J4];
__device__ float  g_P1[VMAX * CAT];
__device__ float  g_P2[VMAX * CAT];
__device__ float4 g_P12[VMAX * VMAX * J4];
__device__ int    g_pair[EMAX];              // pair index premultiplied by J4

// ---------------------------------------------------------------------------
__global__ void prep_tables(const float* __restrict__ emb,
                            const float* __restrict__ dW,
                            const float* __restrict__ eW,
                            int V) {
    const int bid = blockIdx.x;
    const int j   = threadIdx.x;          // 0..271
    if (bid < V) {
        __shared__ float sh_emb[D];
        if (j < D) sh_emb[j] = emb[bid * D + j];
        __syncthreads();
        const float4* wrow = reinterpret_cast<const float4*>(dW + (long long)j * CAT);
        float a1 = 0.f, a2 = 0.f;
#pragma unroll
        for (int k4 = 0; k4 < D / 4; ++k4) {
            float4 t = wrow[k4];
            a1 = fmaf(sh_emb[4 * k4 + 0], t.x, a1);
            a1 = fmaf(sh_emb[4 * k4 + 1], t.y, a1);
            a1 = fmaf(sh_emb[4 * k4 + 2], t.z, a1);
            a1 = fmaf(sh_emb[4 * k4 + 3], t.w, a1);
        }
#pragma unroll
        for (int k4 = 0; k4 < D / 4; ++k4) {
            float4 t = wrow[D / 4 + k4];
            a2 = fmaf(sh_emb[4 * k4 + 0], t.x, a2);
            a2 = fmaf(sh_emb[4 * k4 + 1], t.y, a2);
            a2 = fmaf(sh_emb[4 * k4 + 2], t.z, a2);
            a2 = fmaf(sh_emb[4 * k4 + 3], t.w, a2);
        }
        g_P1[bid * CAT + j] = a1;
        g_P2[bid * CAT + j] = a2;
    } else {
        const int r = bid - V;
        float a = 0.f;
#pragma unroll
        for (int i = 0; i < RBF; ++i)
            a = fmaf(eW[i * RBF + r], dW[(long long)j * CAT + 2 * D + i], a);
        reinterpret_cast<float*>(g_W3)[r * CAT + j] = a;
    }
}

// ---------------------------------------------------------------------------
__global__ void prep_pairs(const float* __restrict__ b, int V) {
    const int bid = blockIdx.x;
    const int vs  = bid / V;
    const int vd  = bid - vs * V;
    const int j   = threadIdx.x;
    float val = g_P1[vs * CAT + j] + g_P2[vd * CAT + j] + b[j];
    reinterpret_cast<float*>(g_P12)[(long long)bid * CAT + j] = val;
}

// ---------------------------------------------------------------------------
__global__ void prep_pair_idx(const int* __restrict__ z,
                              const int* __restrict__ nbr,
                              int E, int V) {
    int e = blockIdx.x * blockDim.x + threadIdx.x;
    if (e < E) {
        int2 nn = reinterpret_cast<const int2*>(nbr)[e];
        g_pair[e] = (__ldg(&z[nn.x]) * V + __ldg(&z[nn.y])) * J4;
    }
}

// ---------------------------------------------------------------------------
// Hot kernel. block = (68, 4): tx = float4 column, ty = edge slot.
// 2 independent edges per thread per iteration; pair indices for the NEXT
// iteration are prefetched; no shared memory, no __syncthreads.
__global__ void __launch_bounds__(272)
edge_main(const float4* __restrict__ e4, float4* __restrict__ out4, int E) {
    const int tx = threadIdx.x;            // 0..67
    const int ty = threadIdx.y;            // 0..3

    float4 w[RBF];
#pragma unroll
    for (int r = 0; r < RBF; ++r) w[r] = g_W3[r * J4 + tx];

    const int stride = gridDim.x * 8;
    int base = blockIdx.x * 8;
    if (base >= E) return;

    int e0 = base + ty;
    int e1 = base + 4 + ty;
    int p0 = (e0 < E) ? __ldg(&g_pair[e0]) : 0;
    int p1 = (e1 < E) ? __ldg(&g_pair[e1]) : 0;

    for (; base < E; base += stride) {
        const bool v0 = (e0 < E);
        const bool v1 = (e1 < E);

        // ---- issue all long-latency loads for this iteration ----
        float4 acc0 = g_P12[p0 + tx];               // L2, coalesced
        float4 acc1 = v1 ? g_P12[p1 + tx] : make_float4(0, 0, 0, 0);

        float4 a0 = __ldg(&e4[(long long)e0 * 4 + 0]);   // warp-broadcast, L1
        float4 a1 = __ldg(&e4[(long long)e0 * 4 + 1]);
        float4 a2 = __ldg(&e4[(long long)e0 * 4 + 2]);
        float4 a3 = __ldg(&e4[(long long)e0 * 4 + 3]);
        long long eb1 = (long long)(v1 ? e1 : e0) * 4;
        float4 b0 = __ldg(&e4[eb1 + 0]);
        float4 b1 = __ldg(&e4[eb1 + 1]);
        float4 b2 = __ldg(&e4[eb1 + 2]);
        float4 b3 = __ldg(&e4[eb1 + 3]);

        // ---- prefetch next iteration's pair indices ----
        int ne0 = e0 + stride, ne1 = e1 + stride;
        int np0 = (ne0 < E) ? __ldg(&g_pair[ne0]) : 0;
        int np1 = (ne1 < E) ? __ldg(&g_pair[ne1]) : 0;

        // ---- edge 0 ----
        {
            const float er[RBF] = {a0.x, a0.y, a0.z, a0.w, a1.x, a1.y, a1.z, a1.w,
                                   a2.x, a2.y, a2.z, a2.w, a3.x, a3.y, a3.z, a3.w};
#pragma unroll
            for (int r = 0; r < RBF; ++r) {
                acc0.x = fmaf(er[r], w[r].x, acc0.x);
                acc0.y = fmaf(er[r], w[r].y, acc0.y);
                acc0.z = fmaf(er[r], w[r].z, acc0.z);
                acc0.w = fmaf(er[r], w[r].w, acc0.w);
            }
            acc0.x = acc0.x / (1.f + __expf(-acc0.x));
            acc0.y = acc0.y / (1.f + __expf(-acc0.y));
            acc0.z = acc0.z / (1.f + __expf(-acc0.z));
            acc0.w = acc0.w / (1.f + __expf(-acc0.w));
            if (v0) __stcs(&out4[(long long)e0 * J4 + tx], acc0);
        }
        // ---- edge 1 ----
        {
            const float er[RBF] = {b0.x, b0.y, b0.z, b0.w, b1.x, b1.y, b1.z, b1.w,
                                   b2.x, b2.y, b2.z, b2.w, b3.x, b3.y, b3.z, b3.w};
#pragma unroll
            for (int r = 0; r < RBF; ++r) {
                acc1.x = fmaf(er[r], w[r].x, acc1.x);
                acc1.y = fmaf(er[r], w[r].y, acc1.y);
                acc1.z = fmaf(er[r], w[r].z, acc1.z);
                acc1.w = fmaf(er[r], w[r].w, acc1.w);
            }
            acc1.x = acc1.x / (1.f + __expf(-acc1.x));
            acc1.y = acc1.y / (1.f + __expf(-acc1.y));
            acc1.z = acc1.z / (1.f + __expf(-acc1.z));
            acc1.w = acc1.w / (1.f + __expf(-acc1.w));
            if (v1) __stcs(&out4[(long long)e1 * J4 + tx], acc1);
        }

        e0 = ne0; e1 = ne1; p0 = np0; p1 = np1;
    }
}

// ---------------------------------------------------------------------------
extern "C" void kernel_launch(void* const* d_in, const int* in_sizes, int n_in,
                              void* d_out, int out_size) {
    const float* e_rbf  = (const float*)d_in[0];
    const int*   z      = (const int*)  d_in[1];
    const int*   nbr    = (const int*)  d_in[2];
    const float* edge_W = (const float*)d_in[3];
    const float* emb    = (const float*)d_in[4];
    const float* dW     = (const float*)d_in[5];
    const float* db     = (const float*)d_in[6];
    float* out = (float*)d_out;

    const int E = in_sizes[0] / RBF;     // 800000
    const int V = in_sizes[4] / D;       // 100

    prep_tables<<<V + RBF, CAT>>>(emb, dW, edge_W, V);
    prep_pairs<<<V * V, CAT>>>(db, V);
    prep_pair_idx<<<(E + 255) / 256, 256>>>(z, nbr, E, V);

    // 7 CTAs/SM (59.5/64 warps): occupancy was the R2/R3 bottleneck (grid=296
    // pinned us at 2 CTAs/SM regardless of registers).
    int grid = 148 * 7;
    int maxg = (E + 7) / 8;
    if (grid > maxg) grid = maxg;

    dim3 blk(J4, 4);
    edge_main<<<grid, blk>>>(reinterpret_cast<const float4*>(e_rbf),
                             reinterpret_cast<float4*>(out), E);
}

// round 6
// speedup vs baseline: 2.0351x; 2.0351x over previous
#include <cuda_runtime.h>

// EmbeddingBlock: out = swish( [emb[z[s]] | emb[z[d]] | e_rbf@edge_W^T] @ dense_W^T + b )
//
// Factorization (VOCAB=100 distinct embedding rows):
//   P12[vs][vd] = emb[vs]@W[:, :128]^T + emb[vd]@W[:,128:256]^T + b  (100^2 x 272, L2-resident)
//   W3eff       = edge_W^T @ W[:,256:272]^T                          (16 x 272)
// Per edge: out = swish( P12[pair[e]] + e_rbf[e] @ W3eff )
// R6: W3 moved to SMEM (frees 64 regs/thread), 4 edges/thread/iter sharing
// each w LDS, __launch_bounds__(272,3) -> 3 CTAs/SM (occ 40% vs 28% cap before).

#define D    128
#define RBF  16
#define CAT  272
#define J4   68
#define VMAX 128
#define EMAX 1048576

__device__ float4 g_W3[RBF * J4];            // [r][j4]
__device__ float  g_P1[VMAX * CAT];
__device__ float  g_P2[VMAX * CAT];
__device__ float4 g_P12[VMAX * VMAX * J4];
__device__ int    g_pair[EMAX];              // pair row index premultiplied by J4

// ---------------------------------------------------------------------------
__global__ void prep_tables(const float* __restrict__ emb,
                            const float* __restrict__ dW,
                            const float* __restrict__ eW,
                            int V) {
    const int bid = blockIdx.x;
    const int j   = threadIdx.x;          // 0..271
    if (bid < V) {
        __shared__ float sh_emb[D];
        if (j < D) sh_emb[j] = emb[bid * D + j];
        __syncthreads();
        const float4* wrow = reinterpret_cast<const float4*>(dW + (long long)j * CAT);
        float a1 = 0.f, a2 = 0.f;
#pragma unroll
        for (int k4 = 0; k4 < D / 4; ++k4) {
            float4 t = wrow[k4];
            a1 = fmaf(sh_emb[4 * k4 + 0], t.x, a1);
            a1 = fmaf(sh_emb[4 * k4 + 1], t.y, a1);
            a1 = fmaf(sh_emb[4 * k4 + 2], t.z, a1);
            a1 = fmaf(sh_emb[4 * k4 + 3], t.w, a1);
        }
#pragma unroll
        for (int k4 = 0; k4 < D / 4; ++k4) {
            float4 t = wrow[D / 4 + k4];
            a2 = fmaf(sh_emb[4 * k4 + 0], t.x, a2);
            a2 = fmaf(sh_emb[4 * k4 + 1], t.y, a2);
            a2 = fmaf(sh_emb[4 * k4 + 2], t.z, a2);
            a2 = fmaf(sh_emb[4 * k4 + 3], t.w, a2);
        }
        g_P1[bid * CAT + j] = a1;
        g_P2[bid * CAT + j] = a2;
    } else {
        const int r = bid - V;
        float a = 0.f;
#pragma unroll
        for (int i = 0; i < RBF; ++i)
            a = fmaf(eW[i * RBF + r], dW[(long long)j * CAT + 2 * D + i], a);
        reinterpret_cast<float*>(g_W3)[r * CAT + j] = a;
    }
}

// ---------------------------------------------------------------------------
__global__ void prep_pairs(const float* __restrict__ b, int V) {
    const int bid = blockIdx.x;
    const int vs  = bid / V;
    const int vd  = bid - vs * V;
    const int j   = threadIdx.x;
    float val = g_P1[vs * CAT + j] + g_P2[vd * CAT + j] + b[j];
    reinterpret_cast<float*>(g_P12)[(long long)bid * CAT + j] = val;
}

// ---------------------------------------------------------------------------
__global__ void prep_pair_idx(const int* __restrict__ z,
                              const int* __restrict__ nbr,
                              int E, int V) {
    int e = blockIdx.x * blockDim.x + threadIdx.x;
    if (e < E) {
        int2 nn = reinterpret_cast<const int2*>(nbr)[e];
        g_pair[e] = (__ldg(&z[nn.x]) * V + __ldg(&z[nn.y])) * J4;
    }
}

// ---------------------------------------------------------------------------
// Hot kernel. block = (68, 4): tx = float4 column, ty = edge group.
// 4 edges per thread per iteration. W3 lives in SMEM; each rbf-chunk of
// 4 LDS.128 w-loads is reused across all 4 edges (4.35 KB LDS / edge).
__global__ void __launch_bounds__(272, 3)
edge_main(const float4* __restrict__ e4, float4* __restrict__ out4, int E) {
    __shared__ float4 w_s[RBF * J4];       // 17408 B

    const int tx  = threadIdx.x;           // 0..67
    const int ty  = threadIdx.y;           // 0..3
    const int tid = ty * J4 + tx;

#pragma unroll
    for (int i = tid; i < RBF * J4; i += 272) w_s[i] = g_W3[i];
    __syncthreads();

    const int stride = gridDim.x * 16;
    int base = blockIdx.x * 16;
    if (base >= E) return;

    int e0 = base + ty, e1 = e0 + 4, e2 = e0 + 8, e3 = e0 + 12;
    int p0 = (e0 < E) ? __ldg(&g_pair[e0]) : 0;
    int p1 = (e1 < E) ? __ldg(&g_pair[e1]) : 0;
    int p2 = (e2 < E) ? __ldg(&g_pair[e2]) : 0;
    int p3 = (e3 < E) ? __ldg(&g_pair[e3]) : 0;

    for (; base < E; base += stride) {
        const bool v0 = (e0 < E), v1 = (e1 < E), v2 = (e2 < E), v3 = (e3 < E);

        // ---- 4 independent P12 row loads in flight (L2) ----
        float4 acc0 = g_P12[p0 + tx];
        float4 acc1 = g_P12[p1 + tx];
        float4 acc2 = g_P12[p2 + tx];
        float4 acc3 = g_P12[p3 + tx];

        // ---- prefetch next iteration's pair indices ----
        const int ne0 = e0 + stride, ne1 = e1 + stride,
                  ne2 = e2 + stride, ne3 = e3 + stride;
        const int np0 = (ne0 < E) ? __ldg(&g_pair[ne0]) : 0;
        const int np1 = (ne1 < E) ? __ldg(&g_pair[ne1]) : 0;
        const int np2 = (ne2 < E) ? __ldg(&g_pair[ne2]) : 0;
        const int np3 = (ne3 < E) ? __ldg(&g_pair[ne3]) : 0;

        const long long b0 = (long long)(v0 ? e0 : E - 1) * 4;
        const long long b1 = (long long)(v1 ? e1 : E - 1) * 4;
        const long long b2 = (long long)(v2 ? e2 : E - 1) * 4;
        const long long b3 = (long long)(v3 ? e3 : E - 1) * 4;

        // ---- rbf chunks of 4: one w LDS set shared by 4 edges ----
#pragma unroll
        for (int c = 0; c < 4; ++c) {
            const float4 wa = w_s[(4 * c + 0) * J4 + tx];
            const float4 wb = w_s[(4 * c + 1) * J4 + tx];
            const float4 wc = w_s[(4 * c + 2) * J4 + tx];
            const float4 wd = w_s[(4 * c + 3) * J4 + tx];

            const float4 A = __ldg(&e4[b0 + c]);   // warp-broadcast, L1
            const float4 B = __ldg(&e4[b1 + c]);
            const float4 C = __ldg(&e4[b2 + c]);
            const float4 Dv = __ldg(&e4[b3 + c]);

            acc0.x = fmaf(A.x, wa.x, acc0.x); acc0.y = fmaf(A.x, wa.y, acc0.y);
            acc0.z = fmaf(A.x, wa.z, acc0.z); acc0.w = fmaf(A.x, wa.w, acc0.w);
            acc0.x = fmaf(A.y, wb.x, acc0.x); acc0.y = fmaf(A.y, wb.y, acc0.y);
            acc0.z = fmaf(A.y, wb.z, acc0.z); acc0.w = fmaf(A.y, wb.w, acc0.w);
            acc0.x = fmaf(A.z, wc.x, acc0.x); acc0.y = fmaf(A.z, wc.y, acc0.y);
            acc0.z = fmaf(A.z, wc.z, acc0.z); acc0.w = fmaf(A.z, wc.w, acc0.w);
            acc0.x = fmaf(A.w, wd.x, acc0.x); acc0.y = fmaf(A.w, wd.y, acc0.y);
            acc0.z = fmaf(A.w, wd.z, acc0.z); acc0.w = fmaf(A.w, wd.w, acc0.w);

            acc1.x = fmaf(B.x, wa.x, acc1.x); acc1.y = fmaf(B.x, wa.y, acc1.y);
            acc1.z = fmaf(B.x, wa.z, acc1.z); acc1.w = fmaf(B.x, wa.w, acc1.w);
            acc1.x = fmaf(B.y, wb.x, acc1.x); acc1.y = fmaf(B.y, wb.y, acc1.y);
            acc1.z = fmaf(B.y, wb.z, acc1.z); acc1.w = fmaf(B.y, wb.w, acc1.w);
            acc1.x = fmaf(B.z, wc.x, acc1.x); acc1.y = fmaf(B.z, wc.y, acc1.y);
            acc1.z = fmaf(B.z, wc.z, acc1.z); acc1.w = fmaf(B.z, wc.w, acc1.w);
            acc1.x = fmaf(B.w, wd.x, acc1.x); acc1.y = fmaf(B.w, wd.y, acc1.y);
            acc1.z = fmaf(B.w, wd.z, acc1.z); acc1.w = fmaf(B.w, wd.w, acc1.w);

            acc2.x = fmaf(C.x, wa.x, acc2.x); acc2.y = fmaf(C.x, wa.y, acc2.y);
            acc2.z = fmaf(C.x, wa.z, acc2.z); acc2.w = fmaf(C.x, wa.w, acc2.w);
            acc2.x = fmaf(C.y, wb.x, acc2.x); acc2.y = fmaf(C.y, wb.y, acc2.y);
            acc2.z = fmaf(C.y, wb.z, acc2.z); acc2.w = fmaf(C.y, wb.w, acc2.w);
            acc2.x = fmaf(C.z, wc.x, acc2.x); acc2.y = fmaf(C.z, wc.y, acc2.y);
            acc2.z = fmaf(C.z, wc.z, acc2.z); acc2.w = fmaf(C.z, wc.w, acc2.w);
            acc2.x = fmaf(C.w, wd.x, acc2.x); acc2.y = fmaf(C.w, wd.y, acc2.y);
            acc2.z = fmaf(C.w, wd.z, acc2.z); acc2.w = fmaf(C.w, wd.w, acc2.w);

            acc3.x = fmaf(Dv.x, wa.x, acc3.x); acc3.y = fmaf(Dv.x, wa.y, acc3.y);
            acc3.z = fmaf(Dv.x, wa.z, acc3.z); acc3.w = fmaf(Dv.x, wa.w, acc3.w);
            acc3.x = fmaf(Dv.y, wb.x, acc3.x); acc3.y = fmaf(Dv.y, wb.y, acc3.y);
            acc3.z = fmaf(Dv.y, wb.z, acc3.z); acc3.w = fmaf(Dv.y, wb.w, acc3.w);
            acc3.x = fmaf(Dv.z, wc.x, acc3.x); acc3.y = fmaf(Dv.z, wc.y, acc3.y);
            acc3.z = fmaf(Dv.z, wc.z, acc3.z); acc3.w = fmaf(Dv.z, wc.w, acc3.w);
            acc3.x = fmaf(Dv.w, wd.x, acc3.x); acc3.y = fmaf(Dv.w, wd.y, acc3.y);
            acc3.z = fmaf(Dv.w, wd.z, acc3.z); acc3.w = fmaf(Dv.w, wd.w, acc3.w);
        }

        // ---- swish + store ----
        acc0.x = acc0.x / (1.f + __expf(-acc0.x));
        acc0.y = acc0.y / (1.f + __expf(-acc0.y));
        acc0.z = acc0.z / (1.f + __expf(-acc0.z));
        acc0.w = acc0.w / (1.f + __expf(-acc0.w));
        if (v0) __stcs(&out4[(long long)e0 * J4 + tx], acc0);

        acc1.x = acc1.x / (1.f + __expf(-acc1.x));
        acc1.y = acc1.y / (1.f + __expf(-acc1.y));
        acc1.z = acc1.z / (1.f + __expf(-acc1.z));
        acc1.w = acc1.w / (1.f + __expf(-acc1.w));
        if (v1) __stcs(&out4[(long long)e1 * J4 + tx], acc1);

        acc2.x = acc2.x / (1.f + __expf(-acc2.x));
        acc2.y = acc2.y / (1.f + __expf(-acc2.y));
        acc2.z = acc2.z / (1.f + __expf(-acc2.z));
        acc2.w = acc2.w / (1.f + __expf(-acc2.w));
        if (v2) __stcs(&out4[(long long)e2 * J4 + tx], acc2);

        acc3.x = acc3.x / (1.f + __expf(-acc3.x));
        acc3.y = acc3.y / (1.f + __expf(-acc3.y));
        acc3.z = acc3.z / (1.f + __expf(-acc3.z));
        acc3.w = acc3.w / (1.f + __expf(-acc3.w));
        if (v3) __stcs(&out4[(long long)e3 * J4 + tx], acc3);

        e0 = ne0; e1 = ne1; e2 = ne2; e3 = ne3;
        p0 = np0; p1 = np1; p2 = np2; p3 = np3;
    }
}

// ---------------------------------------------------------------------------
extern "C" void kernel_launch(void* const* d_in, const int* in_sizes, int n_in,
                              void* d_out, int out_size) {
    const float* e_rbf  = (const float*)d_in[0];
    const int*   z      = (const int*)  d_in[1];
    const int*   nbr    = (const int*)  d_in[2];
    const float* edge_W = (const float*)d_in[3];
    const float* emb    = (const float*)d_in[4];
    const float* dW     = (const float*)d_in[5];
    const float* db     = (const float*)d_in[6];
    float* out = (float*)d_out;

    const int E = in_sizes[0] / RBF;     // 800000
    const int V = in_sizes[4] / D;       // 100

    prep_tables<<<V + RBF, CAT>>>(emb, dW, edge_W, V);
    prep_pairs<<<V * V, CAT>>>(db, V);
    prep_pair_idx<<<(E + 255) / 256, 256>>>(z, nbr, E, V);

    // 3 CTAs/SM (RF: 80 regs x 272 threads x 3 = 65280 <= 64K regs), persistent.
    int grid = 148 * 3;
    int maxg = (E + 15) / 16;
    if (grid > maxg) grid = maxg;

    dim3 blk(J4, 4);
    edge_main<<<grid, blk>>>(reinterpret_cast<const float4*>(e_rbf),
                             reinterpret_cast<float4*>(out), E);
}

// round 7
// speedup vs baseline: 2.1570x; 1.0599x over previous
#include <cuda_runtime.h>
#include <cstdint>

// EmbeddingBlock: out = swish( [emb[z[s]] | emb[z[d]] | e_rbf@edge_W^T] @ dense_W^T + b )
//
// Factorization (VOCAB=100 distinct embedding rows):
//   P12[vs][vd] = emb[vs]@W[:, :128]^T + emb[vd]@W[:,128:256]^T + b  (100^2 x 272, L2-resident)
//   W3eff       = edge_W^T @ W[:,256:272]^T                          (16 x 272, SMEM-resident)
// Per edge: out = swish( P12[pair[e]] + e_rbf[e] @ W3eff )
// R7 = R6 + packed fma.rn.f32x2 (halves FFMA instruction count; ptxas never
// auto-fuses, PTX-only) + v2.u64 loads so w/acc are born as 64-bit pairs.

#define D    128
#define RBF  16
#define CAT  272
#define J4   68
#define VMAX 128
#define EMAX 1048576

typedef unsigned long long u64;

__device__ float4 g_W3[RBF * J4];            // [r][j4]
__device__ float  g_P1[VMAX * CAT];
__device__ float  g_P2[VMAX * CAT];
__device__ float4 g_P12[VMAX * VMAX * J4];
__device__ int    g_pair[EMAX];              // pair row index premultiplied by J4

// ---- f32x2 helpers -------------------------------------------------------
__device__ __forceinline__ u64 pack2(float v) {        // {v, v}
    u64 r; asm("mov.b64 %0, {%1, %2};" : "=l"(r) : "f"(v), "f"(v)); return r;
}
__device__ __forceinline__ void unpack2(u64 v, float& lo, float& hi) {
    asm("mov.b64 {%0, %1}, %2;" : "=f"(lo), "=f"(hi) : "l"(v));
}
__device__ __forceinline__ u64 fma2(u64 a, u64 b, u64 c) {   // a*b+c, 2x fp32
    u64 d; asm("fma.rn.f32x2 %0, %1, %2, %3;" : "=l"(d) : "l"(a), "l"(b), "l"(c));
    return d;
}
__device__ __forceinline__ void lds128(uint32_t addr, u64& a, u64& b) {
    asm("ld.shared.v2.u64 {%0, %1}, [%2];" : "=l"(a), "=l"(b) : "r"(addr));
}
__device__ __forceinline__ void ldg128(const float4* p, u64& a, u64& b) {
    asm("ld.global.nc.v2.u64 {%0, %1}, [%2];" : "=l"(a), "=l"(b) : "l"(p));
}
__device__ __forceinline__ uint32_t smem_u32(const void* p) {
    uint32_t a;
    asm("{ .reg .u64 t; cvta.to.shared.u64 t, %1; cvt.u32.u64 %0, t; }"
        : "=r"(a) : "l"(p));
    return a;
}

// ---------------------------------------------------------------------------
__global__ void prep_tables(const float* __restrict__ emb,
                            const float* __restrict__ dW,
                            const float* __restrict__ eW,
                            int V) {
    const int bid = blockIdx.x;
    const int j   = threadIdx.x;          // 0..271
    if (bid < V) {
        __shared__ float sh_emb[D];
        if (j < D) sh_emb[j] = emb[bid * D + j];
        __syncthreads();
        const float4* wrow = reinterpret_cast<const float4*>(dW + (long long)j * CAT);
        float a1 = 0.f, a2 = 0.f;
#pragma unroll
        for (int k4 = 0; k4 < D / 4; ++k4) {
            float4 t = wrow[k4];
            a1 = fmaf(sh_emb[4 * k4 + 0], t.x, a1);
            a1 = fmaf(sh_emb[4 * k4 + 1], t.y, a1);
            a1 = fmaf(sh_emb[4 * k4 + 2], t.z, a1);
            a1 = fmaf(sh_emb[4 * k4 + 3], t.w, a1);
        }
#pragma unroll
        for (int k4 = 0; k4 < D / 4; ++k4) {
            float4 t = wrow[D / 4 + k4];
            a2 = fmaf(sh_emb[4 * k4 + 0], t.x, a2);
            a2 = fmaf(sh_emb[4 * k4 + 1], t.y, a2);
            a2 = fmaf(sh_emb[4 * k4 + 2], t.z, a2);
            a2 = fmaf(sh_emb[4 * k4 + 3], t.w, a2);
        }
        g_P1[bid * CAT + j] = a1;
        g_P2[bid * CAT + j] = a2;
    } else {
        const int r = bid - V;
        float a = 0.f;
#pragma unroll
        for (int i = 0; i < RBF; ++i)
            a = fmaf(eW[i * RBF + r], dW[(long long)j * CAT + 2 * D + i], a);
        reinterpret_cast<float*>(g_W3)[r * CAT + j] = a;
    }
}

// ---------------------------------------------------------------------------
__global__ void prep_pairs(const float* __restrict__ b, int V) {
    const int bid = blockIdx.x;
    const int vs  = bid / V;
    const int vd  = bid - vs * V;
    const int j   = threadIdx.x;
    float val = g_P1[vs * CAT + j] + g_P2[vd * CAT + j] + b[j];
    reinterpret_cast<float*>(g_P12)[(long long)bid * CAT + j] = val;
}

// ---------------------------------------------------------------------------
__global__ void prep_pair_idx(const int* __restrict__ z,
                              const int* __restrict__ nbr,
                              int E, int V) {
    int e = blockIdx.x * blockDim.x + threadIdx.x;
    if (e < E) {
        int2 nn = reinterpret_cast<const int2*>(nbr)[e];
        g_pair[e] = (__ldg(&z[nn.x]) * V + __ldg(&z[nn.y])) * J4;
    }
}

// ---------------------------------------------------------------------------
// swish(x) applied to a u64 pair, result assembled as 2 floats
__device__ __forceinline__ void swish2(u64 v, float& lo, float& hi) {
    float x0, x1;
    unpack2(v, x0, x1);
    lo = x0 / (1.f + __expf(-x0));
    hi = x1 / (1.f + __expf(-x1));
}

// ---------------------------------------------------------------------------
// Hot kernel. block = (68, 4): tx = float4 column, ty = edge group.
// 4 edges per thread per iteration; W3 in SMEM reused across all 4 edges;
// all math in packed fma.rn.f32x2 (2 fp32 per instruction).
__global__ void __launch_bounds__(272, 3)
edge_main(const float4* __restrict__ e4, float4* __restrict__ out4, int E) {
    __shared__ float4 w_s[RBF * J4];       // 17408 B

    const int tx  = threadIdx.x;           // 0..67
    const int ty  = threadIdx.y;           // 0..3
    const int tid = ty * J4 + tx;

#pragma unroll
    for (int i = tid; i < RBF * J4; i += 272) w_s[i] = g_W3[i];
    __syncthreads();

    const uint32_t wbase = smem_u32(w_s) + tx * 16u;   // this thread's column

    const int stride = gridDim.x * 16;
    int base = blockIdx.x * 16;
    if (base >= E) return;

    int e0 = base + ty, e1 = e0 + 4, e2 = e0 + 8, e3 = e0 + 12;
    int p0 = (e0 < E) ? __ldg(&g_pair[e0]) : 0;
    int p1 = (e1 < E) ? __ldg(&g_pair[e1]) : 0;
    int p2 = (e2 < E) ? __ldg(&g_pair[e2]) : 0;
    int p3 = (e3 < E) ? __ldg(&g_pair[e3]) : 0;

    for (; base < E; base += stride) {
        const bool v0 = (e0 < E), v1 = (e1 < E), v2 = (e2 < E), v3 = (e3 < E);

        // ---- 4 independent P12 row loads in flight (L2), as u64 pairs ----
        u64 acc0l, acc0h, acc1l, acc1h, acc2l, acc2h, acc3l, acc3h;
        ldg128(&g_P12[p0 + tx], acc0l, acc0h);
        ldg128(&g_P12[p1 + tx], acc1l, acc1h);
        ldg128(&g_P12[p2 + tx], acc2l, acc2h);
        ldg128(&g_P12[p3 + tx], acc3l, acc3h);

        // ---- prefetch next iteration's pair indices ----
        const int ne0 = e0 + stride, ne1 = e1 + stride,
                  ne2 = e2 + stride, ne3 = e3 + stride;
        const int np0 = (ne0 < E) ? __ldg(&g_pair[ne0]) : 0;
        const int np1 = (ne1 < E) ? __ldg(&g_pair[ne1]) : 0;
        const int np2 = (ne2 < E) ? __ldg(&g_pair[ne2]) : 0;
        const int np3 = (ne3 < E) ? __ldg(&g_pair[ne3]) : 0;

        const long long b0 = (long long)(v0 ? e0 : E - 1) * 4;
        const long long b1 = (long long)(v1 ? e1 : E - 1) * 4;
        const long long b2 = (long long)(v2 ? e2 : E - 1) * 4;
        const long long b3 = (long long)(v3 ? e3 : E - 1) * 4;

        // ---- rbf chunks of 4: one w LDS set shared by 4 edges ----
#pragma unroll
        for (int c = 0; c < 4; ++c) {
            u64 wal, wah, wbl, wbh, wcl, wch, wdl, wdh;
            lds128(wbase + (4 * c + 0) * (J4 * 16), wal, wah);
            lds128(wbase + (4 * c + 1) * (J4 * 16), wbl, wbh);
            lds128(wbase + (4 * c + 2) * (J4 * 16), wcl, wch);
            lds128(wbase + (4 * c + 3) * (J4 * 16), wdl, wdh);

            const float4 A  = __ldg(&e4[b0 + c]);   // warp-broadcast, L1
            const float4 B  = __ldg(&e4[b1 + c]);
            const float4 C  = __ldg(&e4[b2 + c]);
            const float4 Dv = __ldg(&e4[b3 + c]);

            u64 s;
            s = pack2(A.x);  acc0l = fma2(s, wal, acc0l); acc0h = fma2(s, wah, acc0h);
            s = pack2(A.y);  acc0l = fma2(s, wbl, acc0l); acc0h = fma2(s, wbh, acc0h);
            s = pack2(A.z);  acc0l = fma2(s, wcl, acc0l); acc0h = fma2(s, wch, acc0h);
            s = pack2(A.w);  acc0l = fma2(s, wdl, acc0l); acc0h = fma2(s, wdh, acc0h);

            s = pack2(B.x);  acc1l = fma2(s, wal, acc1l); acc1h = fma2(s, wah, acc1h);
            s = pack2(B.y);  acc1l = fma2(s, wbl, acc1l); acc1h = fma2(s, wbh, acc1h);
            s = pack2(B.z);  acc1l = fma2(s, wcl, acc1l); acc1h = fma2(s, wch, acc1h);
            s = pack2(B.w);  acc1l = fma2(s, wdl, acc1l); acc1h = fma2(s, wdh, acc1h);

            s = pack2(C.x);  acc2l = fma2(s, wal, acc2l); acc2h = fma2(s, wah, acc2h);
            s = pack2(C.y);  acc2l = fma2(s, wbl, acc2l); acc2h = fma2(s, wbh, acc2h);
            s = pack2(C.z);  acc2l = fma2(s, wcl, acc2l); acc2h = fma2(s, wch, acc2h);
            s = pack2(C.w);  acc2l = fma2(s, wdl, acc2l); acc2h = fma2(s, wdh, acc2h);

            s = pack2(Dv.x); acc3l = fma2(s, wal, acc3l); acc3h = fma2(s, wah, acc3h);
            s = pack2(Dv.y); acc3l = fma2(s, wbl, acc3l); acc3h = fma2(s, wbh, acc3h);
            s = pack2(Dv.z); acc3l = fma2(s, wcl, acc3l); acc3h = fma2(s, wch, acc3h);
            s = pack2(Dv.w); acc3l = fma2(s, wdl, acc3l); acc3h = fma2(s, wdh, acc3h);
        }

        // ---- swish + store ----
        float4 o;
        swish2(acc0l, o.x, o.y); swish2(acc0h, o.z, o.w);
        if (v0) __stcs(&out4[(long long)e0 * J4 + tx], o);
        swish2(acc1l, o.x, o.y); swish2(acc1h, o.z, o.w);
        if (v1) __stcs(&out4[(long long)e1 * J4 + tx], o);
        swish2(acc2l, o.x, o.y); swish2(acc2h, o.z, o.w);
        if (v2) __stcs(&out4[(long long)e2 * J4 + tx], o);
        swish2(acc3l, o.x, o.y); swish2(acc3h, o.z, o.w);
        if (v3) __stcs(&out4[(long long)e3 * J4 + tx], o);

        e0 = ne0; e1 = ne1; e2 = ne2; e3 = ne3;
        p0 = np0; p1 = np1; p2 = np2; p3 = np3;
    }
}

// ---------------------------------------------------------------------------
extern "C" void kernel_launch(void* const* d_in, const int* in_sizes, int n_in,
                              void* d_out, int out_size) {
    const float* e_rbf  = (const float*)d_in[0];
    const int*   z      = (const int*)  d_in[1];
    const int*   nbr    = (const int*)  d_in[2];
    const float* edge_W = (const float*)d_in[3];
    const float* emb    = (const float*)d_in[4];
    const float* dW     = (const float*)d_in[5];
    const float* db     = (const float*)d_in[6];
    float* out = (float*)d_out;

    const int E = in_sizes[0] / RBF;     // 800000
    const int V = in_sizes[4] / D;       // 100

    prep_tables<<<V + RBF, CAT>>>(emb, dW, edge_W, V);
    prep_pairs<<<V * V, CAT>>>(db, V);
    prep_pair_idx<<<(E + 255) / 256, 256>>>(z, nbr, E, V);

    int grid = 148 * 3;
    int maxg = (E + 15) / 16;
    if (grid > maxg) grid = maxg;

    dim3 blk(J4, 4);
    edge_main<<<grid, blk>>>(reinterpret_cast<const float4*>(e_rbf),
                             reinterpret_cast<float4*>(out), E);
}